// round 7
// baseline (speedup 1.0000x reference)
#include <cuda_runtime.h>
#include <cuda_bf16.h>
#include <cstdint>

typedef unsigned long long ull;

#define Bq 4
#define Sq 4096
#define Eq 1024
#define Hq 64

// Scratch for projected Q, K, V (allocation-free rule: __device__ globals)
__device__ float g_Q[Bq * Sq * Hq];
__device__ float g_K[Bq * Sq * Hq];
__device__ float g_V[Bq * Sq * Hq];

// ---- packed f32x2 helpers ----
__device__ __forceinline__ void ffma2(ull& a, ull x, ull y) {
    asm("fma.rn.f32x2 %0, %1, %2, %0;" : "+l"(a) : "l"(x), "l"(y));
}
__device__ __forceinline__ ull fmul2(ull x, ull y) {
    ull r; asm("mul.rn.f32x2 %0, %1, %2;" : "=l"(r) : "l"(x), "l"(y)); return r;
}
__device__ __forceinline__ ull pack2(float lo, float hi) {
    ull r; asm("mov.b64 %0, {%1, %2};" : "=l"(r) : "f"(lo), "f"(hi)); return r;
}
__device__ __forceinline__ float lo2(ull v) { return __uint_as_float((unsigned)v); }
__device__ __forceinline__ float hi2(ull v) { return __uint_as_float((unsigned)(v >> 32)); }

// ---- cp.async helpers (attn) ----
__device__ __forceinline__ void cpasync16(uint32_t dst, const void* src) {
    asm volatile("cp.async.cg.shared.global [%0], [%1], 16;" :: "r"(dst), "l"(src));
}
__device__ __forceinline__ void cpasync_commit() {
    asm volatile("cp.async.commit_group;");
}
__device__ __forceinline__ void cpasync_wait0() {
    asm volatile("cp.async.wait_group 0;");
}

// XOR-swizzled tile addressing (attn fp32 tiles): chunk' = chunk ^ (row&15)
__device__ __forceinline__ int SWADDR(int r, int c4) {
    return r * 64 + (((c4 ^ (r & 15)) << 2));
}

// SW128-style swizzle on byte offsets within bf16 tiles (128B rows):
// XORs 16B-chunk index (bits 4..6) with (row & 7).
__device__ __forceinline__ uint32_t sw128(uint32_t byte_off) {
    return byte_off ^ ((byte_off >> 3) & 0x70);
}

// ---- warp-level MMA helpers (sm_80+ ISA; works on base sm_103 target) ----
__device__ __forceinline__ void ldmx4(uint32_t* r, uint32_t addr) {
    asm volatile("ldmatrix.sync.aligned.m8n8.x4.shared.b16 {%0,%1,%2,%3}, [%4];"
                 : "=r"(r[0]), "=r"(r[1]), "=r"(r[2]), "=r"(r[3]) : "r"(addr));
}
__device__ __forceinline__ void mma_bf16(float* c, const uint32_t* a,
                                         uint32_t b0, uint32_t b1) {
    asm volatile(
        "mma.sync.aligned.m16n8k16.row.col.f32.bf16.bf16.f32 "
        "{%0,%1,%2,%3}, {%4,%5,%6,%7}, {%8,%9}, {%0,%1,%2,%3};"
        : "+f"(c[0]), "+f"(c[1]), "+f"(c[2]), "+f"(c[3])
        : "r"(a[0]), "r"(a[1]), "r"(a[2]), "r"(a[3]), "r"(b0), "r"(b1));
}

// ============================================================================
// Kernel 1: fused QKV projection via HMMA (mma.sync) bf16 3-term split.
// Grid 128 (m-tiles of 128 rows), 256 threads (8 warps: 4 over M x 2 over N).
// Block tile M=128 x N=192 (Wq|Wk|Wv fused), K-chunk 64 (4 k16 steps).
// Warp tile 32x96: 2 m16 x 12 n8 C fragments, fp32, resident all 16 chunks.
// smem: bf16 hi/lo tiles, SW128 swizzled, conflict-free STS + ldmatrix.
// ============================================================================
#define QKV_SMEM 81920

__global__ __launch_bounds__(256, 1)
void qkv_kernel(const float* __restrict__ x, const float* __restrict__ Wq,
                const float* __restrict__ Wk, const float* __restrict__ Wv)
{
    extern __shared__ char qsm[];
    char* Ahi = qsm;                 // 128r x 64k bf16 = 16KB
    char* Alo = qsm + 16384;
    char* Bhi = qsm + 32768;         // 192n x 64k bf16 = 24KB
    char* Blo = qsm + 57344;
    const uint32_t uAhi = (uint32_t)__cvta_generic_to_shared(Ahi);
    const uint32_t uAlo = (uint32_t)__cvta_generic_to_shared(Alo);
    const uint32_t uBhi = (uint32_t)__cvta_generic_to_shared(Bhi);
    const uint32_t uBlo = (uint32_t)__cvta_generic_to_shared(Blo);

    const int tid    = threadIdx.x;
    const int wid    = tid >> 5;
    const int lane   = tid & 31;
    const int m0     = blockIdx.x * 128;
    const int warp_m = wid & 3;       // m base = warp_m*32
    const int warp_n = wid >> 2;      // n base = warp_n*96

    const int g  = lane >> 3;         // ldmatrix address group
    const int lr = lane & 7;

    const float* Ws[3] = { Wq, Wk, Wv };

    float c[2][12][4];
    #pragma unroll
    for (int mt = 0; mt < 2; mt++)
        #pragma unroll
        for (int nt = 0; nt < 12; nt++)
            #pragma unroll
            for (int e = 0; e < 4; e++) c[mt][nt][e] = 0.0f;

    #pragma unroll 1
    for (int ch = 0; ch < 16; ch++) {
        const int k0 = ch * 64;

        // ---- convert A tile: x[m0..+127][k0..+63] -> bf16 hi/lo smem ----
        {
            float2 va[16];
            #pragma unroll
            for (int i = 0; i < 16; i++) {
                int p = tid + i * 256;            // pair index 0..4095
                int r = p >> 5, k = (p & 31) * 2;
                va[i] = *(const float2*)&x[(size_t)(m0 + r) * Eq + k0 + k];
            }
            #pragma unroll
            for (int i = 0; i < 16; i++) {
                int p = tid + i * 256;
                int r = p >> 5, k = (p & 31) * 2;
                __nv_bfloat16 h0 = __float2bfloat16(va[i].x);
                __nv_bfloat16 h1 = __float2bfloat16(va[i].y);
                __nv_bfloat16 l0 = __float2bfloat16(va[i].x - __bfloat162float(h0));
                __nv_bfloat16 l1 = __float2bfloat16(va[i].y - __bfloat162float(h1));
                uint32_t off = sw128((uint32_t)(r * 128 + k * 2));
                __nv_bfloat162 hv; hv.x = h0; hv.y = h1;
                __nv_bfloat162 lv; lv.x = l0; lv.y = l1;
                *(__nv_bfloat162*)(Ahi + off) = hv;
                *(__nv_bfloat162*)(Alo + off) = lv;
            }
        }
        // ---- convert B tiles: W[k][n] -> smem [n][k] bf16 hi/lo ----
        {
            float2 vb[24];
            #pragma unroll
            for (int i = 0; i < 24; i++) {
                int q = tid + i * 256;            // pair index 0..6143
                int n = q >> 5, kk = (q & 31) * 2;
                const float* W = Ws[n >> 6];
                const int ncol = n & 63;
                vb[i].x = W[(size_t)(k0 + kk) * Hq + ncol];
                vb[i].y = W[(size_t)(k0 + kk + 1) * Hq + ncol];
            }
            #pragma unroll
            for (int i = 0; i < 24; i++) {
                int q = tid + i * 256;
                int n = q >> 5, kk = (q & 31) * 2;
                __nv_bfloat16 h0 = __float2bfloat16(vb[i].x);
                __nv_bfloat16 h1 = __float2bfloat16(vb[i].y);
                __nv_bfloat16 l0 = __float2bfloat16(vb[i].x - __bfloat162float(h0));
                __nv_bfloat16 l1 = __float2bfloat16(vb[i].y - __bfloat162float(h1));
                uint32_t off = sw128((uint32_t)(n * 128 + kk * 2));
                __nv_bfloat162 hv; hv.x = h0; hv.y = h1;
                __nv_bfloat162 lv; lv.x = l0; lv.y = l1;
                *(__nv_bfloat162*)(Bhi + off) = hv;
                *(__nv_bfloat162*)(Blo + off) = lv;
            }
        }
        __syncthreads();   // tiles visible

        // ---- MMA phase: 4 k16 steps, 3-term split ----
        #pragma unroll
        for (int ks = 0; ks < 4; ks++) {
            uint32_t ah[2][4], al[2][4];
            #pragma unroll
            for (int mt = 0; mt < 2; mt++) {
                // A matrices: g0: rows ra..+7,k0-7; g1: ra+8..,k0-7; g2: ra..,k8-15; g3: ra+8..,k8-15
                int row = warp_m * 32 + mt * 16 + lr + ((g & 1) << 3);
                uint32_t off = sw128((uint32_t)(row * 128 + ((g >> 1) << 4) + ks * 32));
                ldmx4(ah[mt], uAhi + off);
                ldmx4(al[mt], uAlo + off);
            }
            #pragma unroll
            for (int np = 0; np < 6; np++) {      // n16 group = 2 n8 tiles
                // B matrices: g0: n..+7,k0-7; g1: n..+7,k8-15; g2: n+8..,k0-7; g3: n+8..,k8-15
                int nrow = warp_n * 96 + np * 16 + lr + ((g >> 1) << 3);
                uint32_t off = sw128((uint32_t)(nrow * 128 + ((g & 1) << 4) + ks * 32));
                uint32_t bh[4], bl[4];
                ldmx4(bh, uBhi + off);
                ldmx4(bl, uBlo + off);
                #pragma unroll
                for (int mt = 0; mt < 2; mt++) {
                    mma_bf16(c[mt][np * 2],     ah[mt], bh[0], bh[1]);  // hi*hi
                    mma_bf16(c[mt][np * 2],     al[mt], bh[0], bh[1]);  // lo*hi
                    mma_bf16(c[mt][np * 2],     ah[mt], bl[0], bl[1]);  // hi*lo
                    mma_bf16(c[mt][np * 2 + 1], ah[mt], bh[2], bh[3]);
                    mma_bf16(c[mt][np * 2 + 1], al[mt], bh[2], bh[3]);
                    mma_bf16(c[mt][np * 2 + 1], ah[mt], bl[2], bl[3]);
                }
            }
        }
        __syncthreads();   // done reading tiles before next chunk overwrites
    }

    // ---- epilogue: C fragments -> g_Q / g_K / g_V ----
    {
        float* outs[3] = { g_Q, g_K, g_V };
        const int crow = lane >> 2;
        const int ccol = (lane & 3) * 2;
        #pragma unroll
        for (int nt = 0; nt < 12; nt++) {
            const int nglob = warp_n * 96 + nt * 8 + ccol;
            float* dst = outs[nglob >> 6];
            const int h = nglob & 63;
            #pragma unroll
            for (int mt = 0; mt < 2; mt++) {
                const int mrow = m0 + warp_m * 32 + mt * 16 + crow;
                float2 v0 = { c[mt][nt][0], c[mt][nt][1] };
                float2 v1 = { c[mt][nt][2], c[mt][nt][3] };
                *(float2*)&dst[(size_t)mrow * Hq + h] = v0;
                *(float2*)&dst[(size_t)(mrow + 8) * Hq + h] = v1;
            }
        }
    }
}

// ============================================================================
// Kernel 2: causal flash attention, fp32 (unchanged from R5 — 294us).
// ============================================================================
__global__ __launch_bounds__(256, 1) void attn_kernel(float* __restrict__ out)
{
    extern __shared__ float sm[];
    float* Qs = sm;                    // 64x64 swizzled
    float* Ks = Qs + 4096;             // 2 x 64x64 (double buffer)
    float* Vs = Ks + 2 * 4096;         // 2 x 64x64
    float* Ps = Vs + 2 * 4096;         // 64x64

    const int tid  = threadIdx.x;
    const int tx   = tid & 15;
    const int ty   = tid >> 4;
    const int b    = blockIdx.y;

    const uint32_t s_Q = (uint32_t)__cvta_generic_to_shared(Qs);
    const uint32_t s_K = (uint32_t)__cvta_generic_to_shared(Ks);
    const uint32_t s_V = (uint32_t)__cvta_generic_to_shared(Vs);

    const int slot_r  = tid >> 4;
    const int slot_c4 = tid & 15;

    #pragma unroll 1
    for (int half = 0; half < 2; half++) {
        const int qt = (half == 0) ? (int)blockIdx.x : 63 - (int)blockIdx.x;

        __syncthreads();

        const float* Qg    = g_Q + ((size_t)b * Sq + (size_t)qt * 64) * Hq;
        const float* Kbase = g_K + (size_t)b * Sq * Hq;
        const float* Vbase = g_V + (size_t)b * Sq * Hq;

        #pragma unroll
        for (int it = 0; it < 4; it++) {
            int r = slot_r + it * 16;
            uint32_t off = (uint32_t)SWADDR(r, slot_c4) * 4u;
            const size_t gg = (size_t)r * 64 + slot_c4 * 4;
            cpasync16(s_Q + off, Qg + gg);
            cpasync16(s_K + off, Kbase + gg);
            cpasync16(s_V + off, Vbase + gg);
        }
        cpasync_commit();

        float m[4], l[4];
        #pragma unroll
        for (int i = 0; i < 4; i++) { m[i] = -1e30f; l[i] = 0.0f; }
        ull o2[4][2] = {};

        cpasync_wait0();
        __syncthreads();

        #pragma unroll 1
        for (int kt = 0; kt <= qt; kt++) {
            const int cur = kt & 1;
            const float* Kb = Ks + cur * 4096;
            const float* Vb = Vs + cur * 4096;

            if (kt < qt) {
                const float* Kg = Kbase + (size_t)(kt + 1) * 64 * Hq;
                const float* Vg = Vbase + (size_t)(kt + 1) * 64 * Hq;
                const uint32_t boff = (uint32_t)(1 - cur) * 4096u * 4u;
                #pragma unroll
                for (int it = 0; it < 4; it++) {
                    int r = slot_r + it * 16;
                    uint32_t off = (uint32_t)SWADDR(r, slot_c4) * 4u;
                    const size_t gg = (size_t)r * 64 + slot_c4 * 4;
                    cpasync16(s_K + boff + off, Kg + gg);
                    cpasync16(s_V + boff + off, Vg + gg);
                }
                cpasync_commit();
            }

            ull acc[4][4] = {};
            #pragma unroll 4
            for (int h4 = 0; h4 < 16; h4++) {
                double2 qd[4], kd[4];
                #pragma unroll
                for (int i = 0; i < 4; i++)
                    qd[i] = *(const double2*)&Qs[SWADDR(ty * 4 + i, h4)];
                #pragma unroll
                for (int u = 0; u < 4; u++)
                    kd[u] = *(const double2*)&Kb[SWADDR(tx + 16 * u, h4)];
                #pragma unroll
                for (int i = 0; i < 4; i++)
                    #pragma unroll
                    for (int u = 0; u < 4; u++) {
                        ffma2(acc[i][u], (ull)__double_as_longlong(qd[i].x),
                                          (ull)__double_as_longlong(kd[u].x));
                        ffma2(acc[i][u], (ull)__double_as_longlong(qd[i].y),
                                          (ull)__double_as_longlong(kd[u].y));
                    }
            }

            const float SCL = 0.125f * 1.44269504089f;
            float fs[4];
            #pragma unroll
            for (int i = 0; i < 4; i++) {
                const int gi = qt * 64 + ty * 4 + i;
                float s[4];
                #pragma unroll
                for (int u = 0; u < 4; u++) {
                    int gj = kt * 64 + tx + 16 * u;
                    float sv = (lo2(acc[i][u]) + hi2(acc[i][u])) * SCL;
                    s[u] = (gj > gi) ? -1e30f : sv;
                }
                float mx = fmaxf(fmaxf(s[0], s[1]), fmaxf(s[2], s[3]));
                #pragma unroll
                for (int off = 8; off > 0; off >>= 1)
                    mx = fmaxf(mx, __shfl_xor_sync(0xffffffffu, mx, off));
                float mnew = fmaxf(m[i], mx);
                float p[4];
                #pragma unroll
                for (int u = 0; u < 4; u++)
                    p[u] = exp2f(s[u] - mnew);
                float ps = (p[0] + p[1]) + (p[2] + p[3]);
                #pragma unroll
                for (int off = 8; off > 0; off >>= 1)
                    ps += __shfl_xor_sync(0xffffffffu, ps, off);
                float f = exp2f(m[i] - mnew);
                l[i] = l[i] * f + ps;
                m[i] = mnew;
                fs[i] = f;
                const int row = ty * 4 + i;
                #pragma unroll
                for (int u = 0; u < 4; u++)
                    Ps[SWADDR(row, (tx >> 2) + 4 * u) + (tx & 3)] = p[u];
            }

            #pragma unroll
            for (int i = 0; i < 4; i++) {
                ull f2 = pack2(fs[i], fs[i]);
                o2[i][0] = fmul2(o2[i][0], f2);
                o2[i][1] = fmul2(o2[i][1], f2);
            }
            __syncthreads();

            #pragma unroll 4
            for (int j4 = 0; j4 < 16; j4++) {
                float4 pv[4];
                #pragma unroll
                for (int i = 0; i < 4; i++)
                    pv[i] = *(const float4*)&Ps[SWADDR(ty * 4 + i, j4)];
                ull v2[4][2];
                #pragma unroll
                for (int jj = 0; jj < 4; jj++) {
                    double2 vv = *(const double2*)&Vb[SWADDR(j4 * 4 + jj, tx)];
                    v2[jj][0] = (ull)__double_as_longlong(vv.x);
                    v2[jj][1] = (ull)__double_as_longlong(vv.y);
                }
                #pragma unroll
                for (int i = 0; i < 4; i++) {
                    const float* pp = (const float*)&pv[i];
                    #pragma unroll
                    for (int jj = 0; jj < 4; jj++) {
                        ull p2 = pack2(pp[jj], pp[jj]);
                        ffma2(o2[i][0], p2, v2[jj][0]);
                        ffma2(o2[i][1], p2, v2[jj][1]);
                    }
                }
            }

            if (kt < qt) cpasync_wait0();
            __syncthreads();
        }

        #pragma unroll
        for (int i = 0; i < 4; i++) {
            int r = ty * 4 + i;
            float inv = 1.0f / l[i];
            float4 res;
            res.x = lo2(o2[i][0]) * inv;
            res.y = hi2(o2[i][0]) * inv;
            res.z = lo2(o2[i][1]) * inv;
            res.w = hi2(o2[i][1]) * inv;
            *(float4*)&out[((size_t)b * Sq + (size_t)qt * 64 + r) * Hq + tx * 4] = res;
        }
    }
}

// ============================================================================
extern "C" void kernel_launch(void* const* d_in, const int* in_sizes, int n_in,
                              void* d_out, int out_size)
{
    const float* x  = (const float*)d_in[0];
    const float* Wq = (const float*)d_in[1];
    const float* Wk = (const float*)d_in[2];
    const float* Wv = (const float*)d_in[3];
    float* out = (float*)d_out;

    cudaFuncSetAttribute(qkv_kernel, cudaFuncAttributeMaxDynamicSharedMemorySize,
                         QKV_SMEM);
    const int attn_smem = 6 * 4096 * (int)sizeof(float);  // 98304 B
    cudaFuncSetAttribute(attn_kernel, cudaFuncAttributeMaxDynamicSharedMemorySize,
                         attn_smem);

    qkv_kernel<<<128, 256, QKV_SMEM>>>(x, Wq, Wk, Wv);
    attn_kernel<<<dim3(32, 4), 256, attn_smem>>>(out);
}

// round 8
// speedup vs baseline: 1.2398x; 1.2398x over previous
#include <cuda_runtime.h>
#include <cuda_bf16.h>
#include <cstdint>

typedef unsigned long long ull;

#define Bq 4
#define Sq 4096
#define Eq 1024
#define Hq 64

// Scratch for projected Q, K, V (allocation-free rule: __device__ globals)
__device__ float g_Q[Bq * Sq * Hq];
__device__ float g_K[Bq * Sq * Hq];
__device__ float g_V[Bq * Sq * Hq];

// ---- packed f32x2 helpers ----
__device__ __forceinline__ void ffma2(ull& a, ull x, ull y) {
    asm("fma.rn.f32x2 %0, %1, %2, %0;" : "+l"(a) : "l"(x), "l"(y));
}
__device__ __forceinline__ ull fmul2(ull x, ull y) {
    ull r; asm("mul.rn.f32x2 %0, %1, %2;" : "=l"(r) : "l"(x), "l"(y)); return r;
}
__device__ __forceinline__ ull pack2(float lo, float hi) {
    ull r; asm("mov.b64 %0, {%1, %2};" : "=l"(r) : "f"(lo), "f"(hi)); return r;
}
__device__ __forceinline__ float lo2(ull v) { return __uint_as_float((unsigned)v); }
__device__ __forceinline__ float hi2(ull v) { return __uint_as_float((unsigned)(v >> 32)); }

// ---- cp.async helpers (attn) ----
__device__ __forceinline__ void cpasync16(uint32_t dst, const void* src) {
    asm volatile("cp.async.cg.shared.global [%0], [%1], 16;" :: "r"(dst), "l"(src));
}
__device__ __forceinline__ void cpasync_commit() {
    asm volatile("cp.async.commit_group;");
}
__device__ __forceinline__ void cpasync_wait0() {
    asm volatile("cp.async.wait_group 0;");
}

// XOR-swizzled tile addressing (attn fp32 tiles): chunk' = chunk ^ (row&15)
__device__ __forceinline__ int SWADDR(int r, int c4) {
    return r * 64 + (((c4 ^ (r & 15)) << 2));
}

// SW128-style swizzle on byte offsets within bf16 tiles (128B rows):
// XORs 16B-chunk index (bits 4..6) with (row & 7).
__device__ __forceinline__ uint32_t sw128(uint32_t byte_off) {
    return byte_off ^ ((byte_off >> 3) & 0x70);
}

// ---- warp-level MMA helpers (sm_80+ ISA; works on base sm_103 target) ----
__device__ __forceinline__ void ldmx4(uint32_t* r, uint32_t addr) {
    asm volatile("ldmatrix.sync.aligned.m8n8.x4.shared.b16 {%0,%1,%2,%3}, [%4];"
                 : "=r"(r[0]), "=r"(r[1]), "=r"(r[2]), "=r"(r[3]) : "r"(addr));
}
__device__ __forceinline__ void ldmx4t(uint32_t* r, uint32_t addr) {
    asm volatile("ldmatrix.sync.aligned.m8n8.x4.trans.shared.b16 {%0,%1,%2,%3}, [%4];"
                 : "=r"(r[0]), "=r"(r[1]), "=r"(r[2]), "=r"(r[3]) : "r"(addr));
}
__device__ __forceinline__ void mma_bf16(float* c, const uint32_t* a,
                                         uint32_t b0, uint32_t b1) {
    asm volatile(
        "mma.sync.aligned.m16n8k16.row.col.f32.bf16.bf16.f32 "
        "{%0,%1,%2,%3}, {%4,%5,%6,%7}, {%8,%9}, {%0,%1,%2,%3};"
        : "+f"(c[0]), "+f"(c[1]), "+f"(c[2]), "+f"(c[3])
        : "r"(a[0]), "r"(a[1]), "r"(a[2]), "r"(a[3]), "r"(b0), "r"(b1));
}

// ============================================================================
// Kernel 1: fused QKV projection via HMMA (mma.sync) bf16 3-term split.
// R7 fix: B tiles stored k-major ([k][n], coalesced LDG + conflict-free STS),
// B fragments loaded via ldmatrix.x4.trans.
// Grid 128 (m-tiles of 128 rows), 256 threads (8 warps: 4 over M x 2 over N).
// Block tile M=128 x N=192 (Wq|Wk|Wv fused), K-chunk 64 (4 k16 steps).
// ============================================================================
#define QKV_SMEM 81920

__global__ __launch_bounds__(256, 1)
void qkv_kernel(const float* __restrict__ x, const float* __restrict__ Wq,
                const float* __restrict__ Wk, const float* __restrict__ Wv)
{
    extern __shared__ char qsm[];
    char* Ahi = qsm;                 // 128r x 64k bf16 = 16KB  ([m][k])
    char* Alo = qsm + 16384;
    char* Bhi = qsm + 32768;         // 3 weights x 64k x 64n bf16 = 24KB ([k][n])
    char* Blo = qsm + 57344;
    const uint32_t uAhi = (uint32_t)__cvta_generic_to_shared(Ahi);
    const uint32_t uAlo = (uint32_t)__cvta_generic_to_shared(Alo);
    const uint32_t uBhi = (uint32_t)__cvta_generic_to_shared(Bhi);
    const uint32_t uBlo = (uint32_t)__cvta_generic_to_shared(Blo);

    const int tid    = threadIdx.x;
    const int wid    = tid >> 5;
    const int lane   = tid & 31;
    const int m0     = blockIdx.x * 128;
    const int warp_m = wid & 3;       // m base = warp_m*32
    const int warp_n = wid >> 2;      // n base = warp_n*96

    const int g  = lane >> 3;         // ldmatrix address group
    const int lr = lane & 7;

    const float* Ws[3] = { Wq, Wk, Wv };

    float c[2][12][4];
    #pragma unroll
    for (int mt = 0; mt < 2; mt++)
        #pragma unroll
        for (int nt = 0; nt < 12; nt++)
            #pragma unroll
            for (int e = 0; e < 4; e++) c[mt][nt][e] = 0.0f;

    #pragma unroll 1
    for (int ch = 0; ch < 16; ch++) {
        const int k0 = ch * 64;

        // ---- convert A tile: x[m0..+127][k0..+63] -> bf16 hi/lo smem [m][k] ----
        {
            float2 va[16];
            #pragma unroll
            for (int i = 0; i < 16; i++) {
                int p = tid + i * 256;            // pair index 0..4095
                int r = p >> 5, k = (p & 31) * 2; // lanes: consecutive k (coalesced)
                va[i] = *(const float2*)&x[(size_t)(m0 + r) * Eq + k0 + k];
            }
            #pragma unroll
            for (int i = 0; i < 16; i++) {
                int p = tid + i * 256;
                int r = p >> 5, k = (p & 31) * 2;
                __nv_bfloat16 h0 = __float2bfloat16(va[i].x);
                __nv_bfloat16 h1 = __float2bfloat16(va[i].y);
                __nv_bfloat16 l0 = __float2bfloat16(va[i].x - __bfloat162float(h0));
                __nv_bfloat16 l1 = __float2bfloat16(va[i].y - __bfloat162float(h1));
                uint32_t off = sw128((uint32_t)(r * 128 + k * 2));
                __nv_bfloat162 hv; hv.x = h0; hv.y = h1;
                __nv_bfloat162 lv; lv.x = l0; lv.y = l1;
                *(__nv_bfloat162*)(Ahi + off) = hv;
                *(__nv_bfloat162*)(Alo + off) = lv;
            }
        }
        // ---- convert B tiles: W[k][n] -> smem [k][n] bf16 hi/lo (coalesced) ----
        #pragma unroll
        for (int w = 0; w < 3; w++) {
            const float* W = Ws[w];
            char* BhiW = Bhi + w * 8192;
            char* BloW = Blo + w * 8192;
            float2 vb[8];
            #pragma unroll
            for (int i = 0; i < 8; i++) {
                int p = tid + i * 256;            // pair index 0..2047
                int k = p >> 5, n = (p & 31) * 2; // lanes: consecutive n (coalesced)
                vb[i] = *(const float2*)&W[(size_t)(k0 + k) * Hq + n];
            }
            #pragma unroll
            for (int i = 0; i < 8; i++) {
                int p = tid + i * 256;
                int k = p >> 5, n = (p & 31) * 2;
                __nv_bfloat16 h0 = __float2bfloat16(vb[i].x);
                __nv_bfloat16 h1 = __float2bfloat16(vb[i].y);
                __nv_bfloat16 l0 = __float2bfloat16(vb[i].x - __bfloat162float(h0));
                __nv_bfloat16 l1 = __float2bfloat16(vb[i].y - __bfloat162float(h1));
                uint32_t off = sw128((uint32_t)(k * 128 + n * 2));
                __nv_bfloat162 hv; hv.x = h0; hv.y = h1;
                __nv_bfloat162 lv; lv.x = l0; lv.y = l1;
                *(__nv_bfloat162*)(BhiW + off) = hv;
                *(__nv_bfloat162*)(BloW + off) = lv;
            }
        }
        __syncthreads();   // tiles visible

        // ---- MMA phase: 4 k16 steps, 3-term split ----
        #pragma unroll
        for (int ks = 0; ks < 4; ks++) {
            uint32_t ah[2][4], al[2][4];
            #pragma unroll
            for (int mt = 0; mt < 2; mt++) {
                // A (row-major [m][k]): g0: m..+7/k0-7; g1: m+8/k0-7; g2: m/k8-15; g3: m+8/k8-15
                int row = warp_m * 32 + mt * 16 + lr + ((g & 1) << 3);
                uint32_t off = sw128((uint32_t)(row * 128 + ((g >> 1) << 4) + ks * 32));
                ldmx4(ah[mt], uAhi + off);
                ldmx4(al[mt], uAlo + off);
            }
            #pragma unroll
            for (int np = 0; np < 6; np++) {      // n16 group = 2 n8 tiles
                const int nglob = warp_n * 96 + np * 16;
                const int w     = nglob >> 6;     // weight (n16 never crosses)
                const int ncol  = nglob & 63;
                // B ([k][n], trans): tiles (k0,n0),(k8,n0),(k0,n8),(k8,n8)
                int krow = ks * 16 + ((g & 1) << 3) + lr;
                uint32_t off = sw128((uint32_t)(krow * 128 + (ncol + ((g >> 1) << 3)) * 2));
                uint32_t bh[4], bl[4];
                ldmx4t(bh, uBhi + w * 8192 + off);
                ldmx4t(bl, uBlo + w * 8192 + off);
                #pragma unroll
                for (int mt = 0; mt < 2; mt++) {
                    mma_bf16(c[mt][np * 2],     ah[mt], bh[0], bh[1]);  // hi*hi
                    mma_bf16(c[mt][np * 2],     al[mt], bh[0], bh[1]);  // lo*hi
                    mma_bf16(c[mt][np * 2],     ah[mt], bl[0], bl[1]);  // hi*lo
                    mma_bf16(c[mt][np * 2 + 1], ah[mt], bh[2], bh[3]);
                    mma_bf16(c[mt][np * 2 + 1], al[mt], bh[2], bh[3]);
                    mma_bf16(c[mt][np * 2 + 1], ah[mt], bl[2], bl[3]);
                }
            }
        }
        __syncthreads();   // done reading tiles before next chunk overwrites
    }

    // ---- epilogue: C fragments -> g_Q / g_K / g_V ----
    {
        float* outs[3] = { g_Q, g_K, g_V };
        const int crow = lane >> 2;
        const int ccol = (lane & 3) * 2;
        #pragma unroll
        for (int nt = 0; nt < 12; nt++) {
            const int nglob = warp_n * 96 + nt * 8 + ccol;
            float* dst = outs[nglob >> 6];
            const int h = nglob & 63;
            #pragma unroll
            for (int mt = 0; mt < 2; mt++) {
                const int mrow = m0 + warp_m * 32 + mt * 16 + crow;
                float2 v0 = { c[mt][nt][0], c[mt][nt][1] };
                float2 v1 = { c[mt][nt][2], c[mt][nt][3] };
                *(float2*)&dst[(size_t)mrow * Hq + h] = v0;
                *(float2*)&dst[(size_t)(mrow + 8) * Hq + h] = v1;
            }
        }
    }
}

// ============================================================================
// Kernel 2: causal flash attention, fp32 (unchanged — 294us).
// ============================================================================
__global__ __launch_bounds__(256, 1) void attn_kernel(float* __restrict__ out)
{
    extern __shared__ float sm[];
    float* Qs = sm;                    // 64x64 swizzled
    float* Ks = Qs + 4096;             // 2 x 64x64 (double buffer)
    float* Vs = Ks + 2 * 4096;         // 2 x 64x64
    float* Ps = Vs + 2 * 4096;         // 64x64

    const int tid  = threadIdx.x;
    const int tx   = tid & 15;
    const int ty   = tid >> 4;
    const int b    = blockIdx.y;

    const uint32_t s_Q = (uint32_t)__cvta_generic_to_shared(Qs);
    const uint32_t s_K = (uint32_t)__cvta_generic_to_shared(Ks);
    const uint32_t s_V = (uint32_t)__cvta_generic_to_shared(Vs);

    const int slot_r  = tid >> 4;
    const int slot_c4 = tid & 15;

    #pragma unroll 1
    for (int half = 0; half < 2; half++) {
        const int qt = (half == 0) ? (int)blockIdx.x : 63 - (int)blockIdx.x;

        __syncthreads();

        const float* Qg    = g_Q + ((size_t)b * Sq + (size_t)qt * 64) * Hq;
        const float* Kbase = g_K + (size_t)b * Sq * Hq;
        const float* Vbase = g_V + (size_t)b * Sq * Hq;

        #pragma unroll
        for (int it = 0; it < 4; it++) {
            int r = slot_r + it * 16;
            uint32_t off = (uint32_t)SWADDR(r, slot_c4) * 4u;
            const size_t gg = (size_t)r * 64 + slot_c4 * 4;
            cpasync16(s_Q + off, Qg + gg);
            cpasync16(s_K + off, Kbase + gg);
            cpasync16(s_V + off, Vbase + gg);
        }
        cpasync_commit();

        float m[4], l[4];
        #pragma unroll
        for (int i = 0; i < 4; i++) { m[i] = -1e30f; l[i] = 0.0f; }
        ull o2[4][2] = {};

        cpasync_wait0();
        __syncthreads();

        #pragma unroll 1
        for (int kt = 0; kt <= qt; kt++) {
            const int cur = kt & 1;
            const float* Kb = Ks + cur * 4096;
            const float* Vb = Vs + cur * 4096;

            if (kt < qt) {
                const float* Kg = Kbase + (size_t)(kt + 1) * 64 * Hq;
                const float* Vg = Vbase + (size_t)(kt + 1) * 64 * Hq;
                const uint32_t boff = (uint32_t)(1 - cur) * 4096u * 4u;
                #pragma unroll
                for (int it = 0; it < 4; it++) {
                    int r = slot_r + it * 16;
                    uint32_t off = (uint32_t)SWADDR(r, slot_c4) * 4u;
                    const size_t gg = (size_t)r * 64 + slot_c4 * 4;
                    cpasync16(s_K + boff + off, Kg + gg);
                    cpasync16(s_V + boff + off, Vg + gg);
                }
                cpasync_commit();
            }

            ull acc[4][4] = {};
            #pragma unroll 4
            for (int h4 = 0; h4 < 16; h4++) {
                double2 qd[4], kd[4];
                #pragma unroll
                for (int i = 0; i < 4; i++)
                    qd[i] = *(const double2*)&Qs[SWADDR(ty * 4 + i, h4)];
                #pragma unroll
                for (int u = 0; u < 4; u++)
                    kd[u] = *(const double2*)&Kb[SWADDR(tx + 16 * u, h4)];
                #pragma unroll
                for (int i = 0; i < 4; i++)
                    #pragma unroll
                    for (int u = 0; u < 4; u++) {
                        ffma2(acc[i][u], (ull)__double_as_longlong(qd[i].x),
                                          (ull)__double_as_longlong(kd[u].x));
                        ffma2(acc[i][u], (ull)__double_as_longlong(qd[i].y),
                                          (ull)__double_as_longlong(kd[u].y));
                    }
            }

            const float SCL = 0.125f * 1.44269504089f;
            float fs[4];
            #pragma unroll
            for (int i = 0; i < 4; i++) {
                const int gi = qt * 64 + ty * 4 + i;
                float s[4];
                #pragma unroll
                for (int u = 0; u < 4; u++) {
                    int gj = kt * 64 + tx + 16 * u;
                    float sv = (lo2(acc[i][u]) + hi2(acc[i][u])) * SCL;
                    s[u] = (gj > gi) ? -1e30f : sv;
                }
                float mx = fmaxf(fmaxf(s[0], s[1]), fmaxf(s[2], s[3]));
                #pragma unroll
                for (int off = 8; off > 0; off >>= 1)
                    mx = fmaxf(mx, __shfl_xor_sync(0xffffffffu, mx, off));
                float mnew = fmaxf(m[i], mx);
                float p[4];
                #pragma unroll
                for (int u = 0; u < 4; u++)
                    p[u] = exp2f(s[u] - mnew);
                float ps = (p[0] + p[1]) + (p[2] + p[3]);
                #pragma unroll
                for (int off = 8; off > 0; off >>= 1)
                    ps += __shfl_xor_sync(0xffffffffu, ps, off);
                float f = exp2f(m[i] - mnew);
                l[i] = l[i] * f + ps;
                m[i] = mnew;
                fs[i] = f;
                const int row = ty * 4 + i;
                #pragma unroll
                for (int u = 0; u < 4; u++)
                    Ps[SWADDR(row, (tx >> 2) + 4 * u) + (tx & 3)] = p[u];
            }

            #pragma unroll
            for (int i = 0; i < 4; i++) {
                ull f2 = pack2(fs[i], fs[i]);
                o2[i][0] = fmul2(o2[i][0], f2);
                o2[i][1] = fmul2(o2[i][1], f2);
            }
            __syncthreads();

            #pragma unroll 4
            for (int j4 = 0; j4 < 16; j4++) {
                float4 pv[4];
                #pragma unroll
                for (int i = 0; i < 4; i++)
                    pv[i] = *(const float4*)&Ps[SWADDR(ty * 4 + i, j4)];
                ull v2[4][2];
                #pragma unroll
                for (int jj = 0; jj < 4; jj++) {
                    double2 vv = *(const double2*)&Vb[SWADDR(j4 * 4 + jj, tx)];
                    v2[jj][0] = (ull)__double_as_longlong(vv.x);
                    v2[jj][1] = (ull)__double_as_longlong(vv.y);
                }
                #pragma unroll
                for (int i = 0; i < 4; i++) {
                    const float* pp = (const float*)&pv[i];
                    #pragma unroll
                    for (int jj = 0; jj < 4; jj++) {
                        ull p2 = pack2(pp[jj], pp[jj]);
                        ffma2(o2[i][0], p2, v2[jj][0]);
                        ffma2(o2[i][1], p2, v2[jj][1]);
                    }
                }
            }

            if (kt < qt) cpasync_wait0();
            __syncthreads();
        }

        #pragma unroll
        for (int i = 0; i < 4; i++) {
            int r = ty * 4 + i;
            float inv = 1.0f / l[i];
            float4 res;
            res.x = lo2(o2[i][0]) * inv;
            res.y = hi2(o2[i][0]) * inv;
            res.z = lo2(o2[i][1]) * inv;
            res.w = hi2(o2[i][1]) * inv;
            *(float4*)&out[((size_t)b * Sq + (size_t)qt * 64 + r) * Hq + tx * 4] = res;
        }
    }
}

// ============================================================================
extern "C" void kernel_launch(void* const* d_in, const int* in_sizes, int n_in,
                              void* d_out, int out_size)
{
    const float* x  = (const float*)d_in[0];
    const float* Wq = (const float*)d_in[1];
    const float* Wk = (const float*)d_in[2];
    const float* Wv = (const float*)d_in[3];
    float* out = (float*)d_out;

    cudaFuncSetAttribute(qkv_kernel, cudaFuncAttributeMaxDynamicSharedMemorySize,
                         QKV_SMEM);
    const int attn_smem = 6 * 4096 * (int)sizeof(float);  // 98304 B
    cudaFuncSetAttribute(attn_kernel, cudaFuncAttributeMaxDynamicSharedMemorySize,
                         attn_smem);

    qkv_kernel<<<128, 256, QKV_SMEM>>>(x, Wq, Wk, Wv);
    attn_kernel<<<dim3(32, 4), 256, attn_smem>>>(out);
}

// round 9
// speedup vs baseline: 2.4803x; 2.0005x over previous
#include <cuda_runtime.h>
#include <cuda_bf16.h>
#include <cstdint>

#define Bq 4
#define Sq 4096
#define Eq 1024
#define Hq 64

// bf16 hi/lo split Q,K,V scratch (written by qkv_kernel, read by attn_kernel)
__device__ __nv_bfloat16 g_Qh[Bq * Sq * Hq];
__device__ __nv_bfloat16 g_Ql[Bq * Sq * Hq];
__device__ __nv_bfloat16 g_Kh[Bq * Sq * Hq];
__device__ __nv_bfloat16 g_Kl[Bq * Sq * Hq];
__device__ __nv_bfloat16 g_Vh[Bq * Sq * Hq];
__device__ __nv_bfloat16 g_Vl[Bq * Sq * Hq];

// ---- cp.async helpers ----
__device__ __forceinline__ void cpasync16(uint32_t dst, const void* src) {
    asm volatile("cp.async.cg.shared.global [%0], [%1], 16;" :: "r"(dst), "l"(src));
}
__device__ __forceinline__ void cpasync_commit() {
    asm volatile("cp.async.commit_group;");
}
__device__ __forceinline__ void cpasync_wait0() {
    asm volatile("cp.async.wait_group 0;");
}
__device__ __forceinline__ void sts32(uint32_t addr, uint32_t v) {
    asm volatile("st.shared.b32 [%0], %1;" :: "r"(addr), "r"(v));
}

// SW128-style swizzle on byte offsets within bf16 tiles (128B rows)
__device__ __forceinline__ uint32_t sw128(uint32_t byte_off) {
    return byte_off ^ ((byte_off >> 3) & 0x70);
}

// ---- warp-level MMA helpers (sm_80+ ISA; works on base sm_103 target) ----
__device__ __forceinline__ void ldmx4(uint32_t* r, uint32_t addr) {
    asm volatile("ldmatrix.sync.aligned.m8n8.x4.shared.b16 {%0,%1,%2,%3}, [%4];"
                 : "=r"(r[0]), "=r"(r[1]), "=r"(r[2]), "=r"(r[3]) : "r"(addr));
}
__device__ __forceinline__ void ldmx4t(uint32_t* r, uint32_t addr) {
    asm volatile("ldmatrix.sync.aligned.m8n8.x4.trans.shared.b16 {%0,%1,%2,%3}, [%4];"
                 : "=r"(r[0]), "=r"(r[1]), "=r"(r[2]), "=r"(r[3]) : "r"(addr));
}
__device__ __forceinline__ void mma_bf16(float* c, const uint32_t* a,
                                         uint32_t b0, uint32_t b1) {
    asm volatile(
        "mma.sync.aligned.m16n8k16.row.col.f32.bf16.bf16.f32 "
        "{%0,%1,%2,%3}, {%4,%5,%6,%7}, {%8,%9}, {%0,%1,%2,%3};"
        : "+f"(c[0]), "+f"(c[1]), "+f"(c[2]), "+f"(c[3])
        : "r"(a[0]), "r"(a[1]), "r"(a[2]), "r"(a[3]), "r"(b0), "r"(b1));
}

__device__ __forceinline__ uint32_t bfpack(float a, float b) {
    __nv_bfloat162 t;
    t.x = __float2bfloat16(a);
    t.y = __float2bfloat16(b);
    return *(uint32_t*)&t;
}

// ============================================================================
// Kernel 1: fused QKV projection via HMMA bf16 3-term split (R7 layout).
// Epilogue now writes bf16 hi/lo Q/K/V to global scratch (no fp32 pass).
// ============================================================================
#define QKV_SMEM 81920

__global__ __launch_bounds__(256, 1)
void qkv_kernel(const float* __restrict__ x, const float* __restrict__ Wq,
                const float* __restrict__ Wk, const float* __restrict__ Wv)
{
    extern __shared__ char qsm[];
    char* Ahi = qsm;                 // 128r x 64k bf16 = 16KB  ([m][k])
    char* Alo = qsm + 16384;
    char* Bhi = qsm + 32768;         // 3 weights x 64k x 64n bf16 ([k][n])
    char* Blo = qsm + 57344;
    const uint32_t uAhi = (uint32_t)__cvta_generic_to_shared(Ahi);
    const uint32_t uAlo = (uint32_t)__cvta_generic_to_shared(Alo);
    const uint32_t uBhi = (uint32_t)__cvta_generic_to_shared(Bhi);
    const uint32_t uBlo = (uint32_t)__cvta_generic_to_shared(Blo);

    const int tid    = threadIdx.x;
    const int wid    = tid >> 5;
    const int lane   = tid & 31;
    const int m0     = blockIdx.x * 128;
    const int warp_m = wid & 3;
    const int warp_n = wid >> 2;
    const int g  = lane >> 3;
    const int lr = lane & 7;

    const float* Ws[3] = { Wq, Wk, Wv };

    float c[2][12][4];
    #pragma unroll
    for (int mt = 0; mt < 2; mt++)
        #pragma unroll
        for (int nt = 0; nt < 12; nt++)
            #pragma unroll
            for (int e = 0; e < 4; e++) c[mt][nt][e] = 0.0f;

    #pragma unroll 1
    for (int ch = 0; ch < 16; ch++) {
        const int k0 = ch * 64;

        {   // A tile convert
            float2 va[16];
            #pragma unroll
            for (int i = 0; i < 16; i++) {
                int p = tid + i * 256;
                int r = p >> 5, k = (p & 31) * 2;
                va[i] = *(const float2*)&x[(size_t)(m0 + r) * Eq + k0 + k];
            }
            #pragma unroll
            for (int i = 0; i < 16; i++) {
                int p = tid + i * 256;
                int r = p >> 5, k = (p & 31) * 2;
                __nv_bfloat16 h0 = __float2bfloat16(va[i].x);
                __nv_bfloat16 h1 = __float2bfloat16(va[i].y);
                __nv_bfloat16 l0 = __float2bfloat16(va[i].x - __bfloat162float(h0));
                __nv_bfloat16 l1 = __float2bfloat16(va[i].y - __bfloat162float(h1));
                uint32_t off = sw128((uint32_t)(r * 128 + k * 2));
                __nv_bfloat162 hv; hv.x = h0; hv.y = h1;
                __nv_bfloat162 lv; lv.x = l0; lv.y = l1;
                *(__nv_bfloat162*)(Ahi + off) = hv;
                *(__nv_bfloat162*)(Alo + off) = lv;
            }
        }
        #pragma unroll
        for (int w = 0; w < 3; w++) {  // B tiles convert ([k][n])
            const float* W = Ws[w];
            char* BhiW = Bhi + w * 8192;
            char* BloW = Blo + w * 8192;
            float2 vb[8];
            #pragma unroll
            for (int i = 0; i < 8; i++) {
                int p = tid + i * 256;
                int k = p >> 5, n = (p & 31) * 2;
                vb[i] = *(const float2*)&W[(size_t)(k0 + k) * Hq + n];
            }
            #pragma unroll
            for (int i = 0; i < 8; i++) {
                int p = tid + i * 256;
                int k = p >> 5, n = (p & 31) * 2;
                __nv_bfloat16 h0 = __float2bfloat16(vb[i].x);
                __nv_bfloat16 h1 = __float2bfloat16(vb[i].y);
                __nv_bfloat16 l0 = __float2bfloat16(vb[i].x - __bfloat162float(h0));
                __nv_bfloat16 l1 = __float2bfloat16(vb[i].y - __bfloat162float(h1));
                uint32_t off = sw128((uint32_t)(k * 128 + n * 2));
                __nv_bfloat162 hv; hv.x = h0; hv.y = h1;
                __nv_bfloat162 lv; lv.x = l0; lv.y = l1;
                *(__nv_bfloat162*)(BhiW + off) = hv;
                *(__nv_bfloat162*)(BloW + off) = lv;
            }
        }
        __syncthreads();

        #pragma unroll
        for (int ks = 0; ks < 4; ks++) {
            uint32_t ah[2][4], al[2][4];
            #pragma unroll
            for (int mt = 0; mt < 2; mt++) {
                int row = warp_m * 32 + mt * 16 + lr + ((g & 1) << 3);
                uint32_t off = sw128((uint32_t)(row * 128 + ((g >> 1) << 4) + ks * 32));
                ldmx4(ah[mt], uAhi + off);
                ldmx4(al[mt], uAlo + off);
            }
            #pragma unroll
            for (int np = 0; np < 6; np++) {
                const int nglob = warp_n * 96 + np * 16;
                const int w     = nglob >> 6;
                const int ncol  = nglob & 63;
                int krow = ks * 16 + ((g & 1) << 3) + lr;
                uint32_t off = sw128((uint32_t)(krow * 128 + (ncol + ((g >> 1) << 3)) * 2));
                uint32_t bh[4], bl[4];
                ldmx4t(bh, uBhi + w * 8192 + off);
                ldmx4t(bl, uBlo + w * 8192 + off);
                #pragma unroll
                for (int mt = 0; mt < 2; mt++) {
                    mma_bf16(c[mt][np * 2],     ah[mt], bh[0], bh[1]);
                    mma_bf16(c[mt][np * 2],     al[mt], bh[0], bh[1]);
                    mma_bf16(c[mt][np * 2],     ah[mt], bl[0], bl[1]);
                    mma_bf16(c[mt][np * 2 + 1], ah[mt], bh[2], bh[3]);
                    mma_bf16(c[mt][np * 2 + 1], al[mt], bh[2], bh[3]);
                    mma_bf16(c[mt][np * 2 + 1], ah[mt], bl[2], bl[3]);
                }
            }
        }
        __syncthreads();
    }

    // ---- epilogue: C frags -> bf16 hi/lo global Q/K/V ----
    {
        __nv_bfloat16* outsH[3] = { g_Qh, g_Kh, g_Vh };
        __nv_bfloat16* outsL[3] = { g_Ql, g_Kl, g_Vl };
        const int crow = lane >> 2;
        const int ccol = (lane & 3) * 2;
        #pragma unroll
        for (int nt = 0; nt < 12; nt++) {
            const int nglob = warp_n * 96 + nt * 8 + ccol;
            __nv_bfloat16* dh = outsH[nglob >> 6];
            __nv_bfloat16* dl = outsL[nglob >> 6];
            const int h = nglob & 63;
            #pragma unroll
            for (int mt = 0; mt < 2; mt++) {
                const int mrow = m0 + warp_m * 32 + mt * 16 + crow;
                #pragma unroll
                for (int rr = 0; rr < 2; rr++) {
                    float v0 = c[mt][nt][rr * 2 + 0];
                    float v1 = c[mt][nt][rr * 2 + 1];
                    __nv_bfloat16 h0 = __float2bfloat16(v0);
                    __nv_bfloat16 h1 = __float2bfloat16(v1);
                    __nv_bfloat16 l0 = __float2bfloat16(v0 - __bfloat162float(h0));
                    __nv_bfloat16 l1 = __float2bfloat16(v1 - __bfloat162float(h1));
                    size_t o = (size_t)(mrow + rr * 8) * Hq + h;
                    __nv_bfloat162 hv; hv.x = h0; hv.y = h1;
                    __nv_bfloat162 lv; lv.x = l0; lv.y = l1;
                    *(__nv_bfloat162*)&dh[o] = hv;
                    *(__nv_bfloat162*)&dl[o] = lv;
                }
            }
        }
    }
}

// ============================================================================
// Kernel 2: causal flash attention via HMMA bf16 3-term split.
// 256 threads, 8 warps = 4(M16) x 2(N32). Tiles 64x64. Frag-register softmax
// with quad-shuffle partials + smem cross-warp combine. K/V double-buffered
// bf16 hi/lo via cp.async. Block handles q-tiles qt and 63-qt (65 iters).
// ============================================================================
// smem layout (bytes): Qh 0, Ql 8192, Kh[2] 16384, Kl[2] 32768, Vh[2] 49152,
// Vl[2] 65536, Ph 81920, Pl 90112, stats 98304 (m,l,pm[2],ps[2] floats)
#define ATTN_SMEM (98304 + 384 * 4)

__global__ __launch_bounds__(256, 1) void attn_kernel(float* __restrict__ out)
{
    extern __shared__ char smb[];
    const uint32_t base = (uint32_t)__cvta_generic_to_shared(smb);
    const uint32_t uQH = base,          uQL = base + 8192;
    const uint32_t uKH = base + 16384,  uKL = base + 32768;
    const uint32_t uVH = base + 49152,  uVL = base + 65536;
    const uint32_t uPH = base + 81920,  uPL = base + 90112;
    float* mrow = (float*)(smb + 98304);
    float* lrow = mrow + 64;
    float* pm   = lrow + 64;   // [2][64]
    float* ps   = pm + 128;    // [2][64]

    const int tid  = threadIdx.x;
    const int lane = tid & 31;
    const int wid  = tid >> 5;
    const int wm   = wid & 3;           // m16 block: rows wm*16..+15
    const int wn   = wid >> 2;          // n32 block: cols wn*32..+31
    const int g    = lane >> 3;
    const int lr   = lane & 7;
    const int r0   = lane >> 2;         // frag row within m16
    const int cc   = (lane & 3) * 2;    // frag col pair
    const int b    = blockIdx.y;

    const int rowA = wm * 16 + r0;
    const int rowB = rowA + 8;

    #pragma unroll 1
    for (int half = 0; half < 2; half++) {
        const int qt = (half == 0) ? (int)blockIdx.x : 63 - (int)blockIdx.x;
        __syncthreads();   // previous half fully done with smem

        const size_t qoff   = ((size_t)b * Sq + (size_t)qt * 64) * Hq;
        const size_t kvbase = (size_t)b * Sq * Hq;

        // prologue: Q hi/lo + kv-tile 0 (buffer 0)
        #pragma unroll
        for (int it = 0; it < 2; it++) {
            int chunk = tid + it * 256;
            int r = chunk >> 3, c16 = chunk & 7;
            uint32_t off = sw128((uint32_t)(r * 128 + c16 * 16));
            size_t gsrc = (size_t)r * 64 + c16 * 8;
            cpasync16(uQH + off, g_Qh + qoff + gsrc);
            cpasync16(uQL + off, g_Ql + qoff + gsrc);
            cpasync16(uKH + off, g_Kh + kvbase + gsrc);
            cpasync16(uKL + off, g_Kl + kvbase + gsrc);
            cpasync16(uVH + off, g_Vh + kvbase + gsrc);
            cpasync16(uVL + off, g_Vl + kvbase + gsrc);
        }
        cpasync_commit();
        if (tid < 64) { mrow[tid] = -1e30f; lrow[tid] = 0.0f; }

        float c[4][4];
        #pragma unroll
        for (int np = 0; np < 4; np++)
            #pragma unroll
            for (int e = 0; e < 4; e++) c[np][e] = 0.0f;

        cpasync_wait0();
        __syncthreads();

        #pragma unroll 1
        for (int kt = 0; kt <= qt; kt++) {
            const int cur = kt & 1;
            const uint32_t kh = uKH + cur * 8192, kl = uKL + cur * 8192;
            const uint32_t vh = uVH + cur * 8192, vl = uVL + cur * 8192;

            if (kt < qt) {   // prefetch next kv tile into alternate buffer
                size_t nsrc = kvbase + (size_t)(kt + 1) * 64 * Hq;
                uint32_t boff = (uint32_t)(1 - cur) * 8192;
                #pragma unroll
                for (int it = 0; it < 2; it++) {
                    int chunk = tid + it * 256;
                    int r = chunk >> 3, c16 = chunk & 7;
                    uint32_t off = sw128((uint32_t)(r * 128 + c16 * 16));
                    size_t gsrc = (size_t)r * 64 + c16 * 8;
                    cpasync16(uKH + boff + off, g_Kh + nsrc + gsrc);
                    cpasync16(uKL + boff + off, g_Kl + nsrc + gsrc);
                    cpasync16(uVH + boff + off, g_Vh + nsrc + gsrc);
                    cpasync16(uVL + boff + off, g_Vl + nsrc + gsrc);
                }
                cpasync_commit();
            }

            // ---- S = Q K^T (3-term HMMA) ----
            float s[4][4];
            #pragma unroll
            for (int np = 0; np < 4; np++)
                #pragma unroll
                for (int e = 0; e < 4; e++) s[np][e] = 0.0f;

            #pragma unroll
            for (int ks = 0; ks < 4; ks++) {
                uint32_t ah[4], al[4];
                {
                    uint32_t off = sw128((uint32_t)((wm * 16 + lr + ((g & 1) << 3)) * 128
                                                    + ((g >> 1) << 4) + ks * 32));
                    ldmx4(ah, uQH + off);
                    ldmx4(al, uQL + off);
                }
                #pragma unroll
                for (int ng = 0; ng < 2; ng++) {
                    int nb = wn * 32 + ng * 16;
                    uint32_t off = sw128((uint32_t)((nb + ((g >> 1) << 3) + lr) * 128
                                                    + ((g & 1) << 4) + ks * 32));
                    uint32_t bh[4], bl[4];
                    ldmx4(bh, kh + off);
                    ldmx4(bl, kl + off);
                    mma_bf16(s[ng * 2],     ah, bh[0], bh[1]);
                    mma_bf16(s[ng * 2],     al, bh[0], bh[1]);
                    mma_bf16(s[ng * 2],     ah, bl[0], bl[1]);
                    mma_bf16(s[ng * 2 + 1], ah, bh[2], bh[3]);
                    mma_bf16(s[ng * 2 + 1], al, bh[2], bh[3]);
                    mma_bf16(s[ng * 2 + 1], ah, bl[2], bl[3]);
                }
            }

            // ---- scale + causal mask ----
            const float SCL = 0.125f * 1.44269504089f;
            if (kt == qt) {
                const int gi0 = qt * 64 + rowA;
                const int gi1 = gi0 + 8;
                #pragma unroll
                for (int np = 0; np < 4; np++) {
                    int gj = kt * 64 + wn * 32 + np * 8 + cc;
                    s[np][0] = (gj     > gi0) ? -1e30f : s[np][0] * SCL;
                    s[np][1] = (gj + 1 > gi0) ? -1e30f : s[np][1] * SCL;
                    s[np][2] = (gj     > gi1) ? -1e30f : s[np][2] * SCL;
                    s[np][3] = (gj + 1 > gi1) ? -1e30f : s[np][3] * SCL;
                }
            } else {
                #pragma unroll
                for (int np = 0; np < 4; np++)
                    #pragma unroll
                    for (int e = 0; e < 4; e++) s[np][e] *= SCL;
            }

            // ---- partial rowmax (quad shuffle), write pm ----
            float rm0 = -1e30f, rm1 = -1e30f;
            #pragma unroll
            for (int np = 0; np < 4; np++) {
                rm0 = fmaxf(rm0, fmaxf(s[np][0], s[np][1]));
                rm1 = fmaxf(rm1, fmaxf(s[np][2], s[np][3]));
            }
            rm0 = fmaxf(rm0, __shfl_xor_sync(0xffffffffu, rm0, 1));
            rm0 = fmaxf(rm0, __shfl_xor_sync(0xffffffffu, rm0, 2));
            rm1 = fmaxf(rm1, __shfl_xor_sync(0xffffffffu, rm1, 1));
            rm1 = fmaxf(rm1, __shfl_xor_sync(0xffffffffu, rm1, 2));
            if ((lane & 3) == 0) {
                pm[wn * 64 + rowA] = rm0;
                pm[wn * 64 + rowB] = rm1;
            }
            __syncthreads();   // SYNC0: pm visible

            // ---- softmax: p = exp2(s - mnew), partial rowsum, P->smem ----
            const float mo0 = mrow[rowA], mo1 = mrow[rowB];
            const float mn0 = fmaxf(mo0, fmaxf(pm[rowA], pm[64 + rowA]));
            const float mn1 = fmaxf(mo1, fmaxf(pm[rowB], pm[64 + rowB]));
            float rs0 = 0.0f, rs1 = 0.0f;
            #pragma unroll
            for (int np = 0; np < 4; np++) {
                s[np][0] = exp2f(s[np][0] - mn0);
                s[np][1] = exp2f(s[np][1] - mn0);
                s[np][2] = exp2f(s[np][2] - mn1);
                s[np][3] = exp2f(s[np][3] - mn1);
                rs0 += s[np][0] + s[np][1];
                rs1 += s[np][2] + s[np][3];
                // bf16 hi/lo split of P, store to smem
                int col = wn * 32 + np * 8 + cc;
                float h0f = __bfloat162float(__float2bfloat16(s[np][0]));
                float h1f = __bfloat162float(__float2bfloat16(s[np][1]));
                float h2f = __bfloat162float(__float2bfloat16(s[np][2]));
                float h3f = __bfloat162float(__float2bfloat16(s[np][3]));
                uint32_t offA = sw128((uint32_t)(rowA * 128 + col * 2));
                uint32_t offB = sw128((uint32_t)(rowB * 128 + col * 2));
                sts32(uPH + offA, bfpack(h0f, h1f));
                sts32(uPH + offB, bfpack(h2f, h3f));
                sts32(uPL + offA, bfpack(s[np][0] - h0f, s[np][1] - h1f));
                sts32(uPL + offB, bfpack(s[np][2] - h2f, s[np][3] - h3f));
            }
            rs0 += __shfl_xor_sync(0xffffffffu, rs0, 1);
            rs0 += __shfl_xor_sync(0xffffffffu, rs0, 2);
            rs1 += __shfl_xor_sync(0xffffffffu, rs1, 1);
            rs1 += __shfl_xor_sync(0xffffffffu, rs1, 2);
            if ((lane & 3) == 0) {
                ps[wn * 64 + rowA] = rs0;
                ps[wn * 64 + rowB] = rs1;
            }
            __syncthreads();   // SYNC1: P + ps visible

            // ---- rescale O frags; update persistent stats ----
            {
                const float f0 = exp2f(mo0 - mn0);
                const float f1 = exp2f(mo1 - mn1);
                #pragma unroll
                for (int np = 0; np < 4; np++) {
                    c[np][0] *= f0; c[np][1] *= f0;
                    c[np][2] *= f1; c[np][3] *= f1;
                }
            }
            if (tid < 64) {
                float mo = mrow[tid];
                float mn = fmaxf(mo, fmaxf(pm[tid], pm[64 + tid]));
                float f  = exp2f(mo - mn);
                lrow[tid] = lrow[tid] * f + ps[tid] + ps[64 + tid];
                mrow[tid] = mn;
            }

            // ---- O += P V (3-term HMMA) ----
            #pragma unroll
            for (int ks = 0; ks < 4; ks++) {
                uint32_t pah[4], pal[4];
                {
                    uint32_t off = sw128((uint32_t)((wm * 16 + lr + ((g & 1) << 3)) * 128
                                                    + ((g >> 1) << 4) + ks * 32));
                    ldmx4(pah, uPH + off);
                    ldmx4(pal, uPL + off);
                }
                #pragma unroll
                for (int ng = 0; ng < 2; ng++) {
                    int nb = wn * 32 + ng * 16;
                    int krow = ks * 16 + ((g & 1) << 3) + lr;
                    uint32_t off = sw128((uint32_t)(krow * 128
                                                    + (nb + ((g >> 1) << 3)) * 2));
                    uint32_t bh[4], bl[4];
                    ldmx4t(bh, vh + off);
                    ldmx4t(bl, vl + off);
                    mma_bf16(c[ng * 2],     pah, bh[0], bh[1]);
                    mma_bf16(c[ng * 2],     pal, bh[0], bh[1]);
                    mma_bf16(c[ng * 2],     pah, bl[0], bl[1]);
                    mma_bf16(c[ng * 2 + 1], pah, bh[2], bh[3]);
                    mma_bf16(c[ng * 2 + 1], pal, bh[2], bh[3]);
                    mma_bf16(c[ng * 2 + 1], pah, bl[2], bl[3]);
                }
            }

            if (kt < qt) cpasync_wait0();
            __syncthreads();   // SYNC2: buffers/stats ready for next iter
        }

        // ---- epilogue: O /= l, write out ----
        {
            const float inv0 = 1.0f / lrow[rowA];
            const float inv1 = 1.0f / lrow[rowB];
            #pragma unroll
            for (int np = 0; np < 4; np++) {
                int hcol = wn * 32 + np * 8 + cc;
                float2 v0 = { c[np][0] * inv0, c[np][1] * inv0 };
                float2 v1 = { c[np][2] * inv1, c[np][3] * inv1 };
                *(float2*)&out[((size_t)b * Sq + (size_t)qt * 64 + rowA) * Hq + hcol] = v0;
                *(float2*)&out[((size_t)b * Sq + (size_t)qt * 64 + rowB) * Hq + hcol] = v1;
            }
        }
    }
}

// ============================================================================
extern "C" void kernel_launch(void* const* d_in, const int* in_sizes, int n_in,
                              void* d_out, int out_size)
{
    const float* x  = (const float*)d_in[0];
    const float* Wq = (const float*)d_in[1];
    const float* Wk = (const float*)d_in[2];
    const float* Wv = (const float*)d_in[3];
    float* out = (float*)d_out;

    cudaFuncSetAttribute(qkv_kernel, cudaFuncAttributeMaxDynamicSharedMemorySize,
                         QKV_SMEM);
    cudaFuncSetAttribute(attn_kernel, cudaFuncAttributeMaxDynamicSharedMemorySize,
                         ATTN_SMEM);

    qkv_kernel<<<128, 256, QKV_SMEM>>>(x, Wq, Wk, Wv);
    attn_kernel<<<dim3(32, 4), 256, ATTN_SMEM>>>(out);
}

// round 10
// speedup vs baseline: 2.5953x; 1.0464x over previous
#include <cuda_runtime.h>
#include <cuda_bf16.h>
#include <cstdint>

#define Bq 4
#define Sq 4096
#define Eq 1024
#define Hq 64

// bf16 hi/lo split Q,K,V scratch (qkv_kernel -> attn_kernel)
__device__ __nv_bfloat16 g_Qh[Bq * Sq * Hq];
__device__ __nv_bfloat16 g_Ql[Bq * Sq * Hq];
__device__ __nv_bfloat16 g_Kh[Bq * Sq * Hq];
__device__ __nv_bfloat16 g_Kl[Bq * Sq * Hq];
__device__ __nv_bfloat16 g_Vh[Bq * Sq * Hq];
__device__ __nv_bfloat16 g_Vl[Bq * Sq * Hq];
// pre-converted weights, [w][k][n] bf16 hi/lo (wprep_kernel -> qkv_kernel)
__device__ __nv_bfloat16 g_Wh[3 * Eq * Hq];
__device__ __nv_bfloat16 g_Wl[3 * Eq * Hq];

// ---- cp.async helpers ----
__device__ __forceinline__ void cpasync16(uint32_t dst, const void* src) {
    asm volatile("cp.async.cg.shared.global [%0], [%1], 16;" :: "r"(dst), "l"(src));
}
__device__ __forceinline__ void cpasync_commit() {
    asm volatile("cp.async.commit_group;");
}
__device__ __forceinline__ void cpasync_wait0() {
    asm volatile("cp.async.wait_group 0;");
}
__device__ __forceinline__ void sts32(uint32_t addr, uint32_t v) {
    asm volatile("st.shared.b32 [%0], %1;" :: "r"(addr), "r"(v));
}

// SW128-style swizzle on byte offsets within 128B-row bf16 tiles
__device__ __forceinline__ uint32_t sw128(uint32_t byte_off) {
    return byte_off ^ ((byte_off >> 3) & 0x70);
}
// swizzle for 256B-row tiles (P): 16B chunk c (0..15) in row r
__device__ __forceinline__ uint32_t swP(int r, int c) {
    return (uint32_t)(r * 256 + ((c ^ (r & 7)) << 4));
}

// ---- warp-level MMA helpers ----
__device__ __forceinline__ void ldmx4(uint32_t* r, uint32_t addr) {
    asm volatile("ldmatrix.sync.aligned.m8n8.x4.shared.b16 {%0,%1,%2,%3}, [%4];"
                 : "=r"(r[0]), "=r"(r[1]), "=r"(r[2]), "=r"(r[3]) : "r"(addr));
}
__device__ __forceinline__ void ldmx4t(uint32_t* r, uint32_t addr) {
    asm volatile("ldmatrix.sync.aligned.m8n8.x4.trans.shared.b16 {%0,%1,%2,%3}, [%4];"
                 : "=r"(r[0]), "=r"(r[1]), "=r"(r[2]), "=r"(r[3]) : "r"(addr));
}
__device__ __forceinline__ void mma_bf16(float* c, const uint32_t* a,
                                         uint32_t b0, uint32_t b1) {
    asm volatile(
        "mma.sync.aligned.m16n8k16.row.col.f32.bf16.bf16.f32 "
        "{%0,%1,%2,%3}, {%4,%5,%6,%7}, {%8,%9}, {%0,%1,%2,%3};"
        : "+f"(c[0]), "+f"(c[1]), "+f"(c[2]), "+f"(c[3])
        : "r"(a[0]), "r"(a[1]), "r"(a[2]), "r"(a[3]), "r"(b0), "r"(b1));
}
__device__ __forceinline__ uint32_t bfpack(float a, float b) {
    __nv_bfloat162 t;
    t.x = __float2bfloat16(a);
    t.y = __float2bfloat16(b);
    return *(uint32_t*)&t;
}

// ============================================================================
// Kernel 0: one-time W fp32 -> bf16 hi/lo, [w][k][n] layout.
// ============================================================================
__global__ __launch_bounds__(256) void wprep_kernel(
    const float* __restrict__ Wq, const float* __restrict__ Wk,
    const float* __restrict__ Wv)
{
    const float* Ws[3] = { Wq, Wk, Wv };
    int g0 = blockIdx.x * 256 + threadIdx.x;
    for (int i = g0; i < 3 * Eq * Hq / 2; i += gridDim.x * 256) {
        int w = i / (Eq * Hq / 2);
        int rem = i - w * (Eq * Hq / 2);
        int k = rem >> 5;
        int n = (rem & 31) * 2;
        float2 v = *(const float2*)&Ws[w][(size_t)k * Hq + n];
        __nv_bfloat16 h0 = __float2bfloat16(v.x);
        __nv_bfloat16 h1 = __float2bfloat16(v.y);
        __nv_bfloat16 l0 = __float2bfloat16(v.x - __bfloat162float(h0));
        __nv_bfloat16 l1 = __float2bfloat16(v.y - __bfloat162float(h1));
        size_t o = (size_t)w * Eq * Hq + (size_t)k * Hq + n;
        __nv_bfloat162 hv; hv.x = h0; hv.y = h1;
        __nv_bfloat162 lv; lv.x = l0; lv.y = l1;
        *(__nv_bfloat162*)&g_Wh[o] = hv;
        *(__nv_bfloat162*)&g_Wl[o] = lv;
    }
}

// ============================================================================
// Kernel 1: fused QKV projection via HMMA bf16 3-term split.
// R9: W tiles cp.async'd from pre-converted global (overlaps A conversion).
// ============================================================================
#define QKV_SMEM 81920

__global__ __launch_bounds__(256, 1)
void qkv_kernel(const float* __restrict__ x)
{
    extern __shared__ char qsm[];
    char* Ahi = qsm;                 // 128r x 64k bf16 = 16KB  ([m][k])
    char* Alo = qsm + 16384;
    const uint32_t uAhi = (uint32_t)__cvta_generic_to_shared(Ahi);
    const uint32_t uAlo = (uint32_t)__cvta_generic_to_shared(Alo);
    const uint32_t uBhi = uAhi + 32768;   // 3 x 64k x 64n bf16 ([k][n])
    const uint32_t uBlo = uAhi + 57344;

    const int tid    = threadIdx.x;
    const int wid    = tid >> 5;
    const int lane   = tid & 31;
    const int m0     = blockIdx.x * 128;
    const int warp_m = wid & 3;
    const int warp_n = wid >> 2;
    const int g  = lane >> 3;
    const int lr = lane & 7;

    float c[2][12][4];
    #pragma unroll
    for (int mt = 0; mt < 2; mt++)
        #pragma unroll
        for (int nt = 0; nt < 12; nt++)
            #pragma unroll
            for (int e = 0; e < 4; e++) c[mt][nt][e] = 0.0f;

    #pragma unroll 1
    for (int ch = 0; ch < 16; ch++) {
        const int k0 = ch * 64;

        // ---- async W tile loads (pre-converted bf16, [k][n]) ----
        #pragma unroll
        for (int it = 0; it < 6; it++) {
            int cidx = tid + it * 256;          // 0..1535
            int w   = cidx >> 9;
            int r   = (cidx >> 3) & 63;
            int c16 = cidx & 7;
            uint32_t off = (uint32_t)(w * 8192) + sw128((uint32_t)(r * 128 + c16 * 16));
            size_t src = (size_t)w * Eq * Hq + (size_t)(k0 + r) * Hq + c16 * 8;
            cpasync16(uBhi + off, g_Wh + src);
            cpasync16(uBlo + off, g_Wl + src);
        }
        cpasync_commit();

        // ---- A tile convert (overlaps W cp.async) ----
        {
            float2 va[16];
            #pragma unroll
            for (int i = 0; i < 16; i++) {
                int p = tid + i * 256;
                int r = p >> 5, k = (p & 31) * 2;
                va[i] = *(const float2*)&x[(size_t)(m0 + r) * Eq + k0 + k];
            }
            #pragma unroll
            for (int i = 0; i < 16; i++) {
                int p = tid + i * 256;
                int r = p >> 5, k = (p & 31) * 2;
                __nv_bfloat16 h0 = __float2bfloat16(va[i].x);
                __nv_bfloat16 h1 = __float2bfloat16(va[i].y);
                __nv_bfloat16 l0 = __float2bfloat16(va[i].x - __bfloat162float(h0));
                __nv_bfloat16 l1 = __float2bfloat16(va[i].y - __bfloat162float(h1));
                uint32_t off = sw128((uint32_t)(r * 128 + k * 2));
                __nv_bfloat162 hv; hv.x = h0; hv.y = h1;
                __nv_bfloat162 lv; lv.x = l0; lv.y = l1;
                *(__nv_bfloat162*)(Ahi + off) = hv;
                *(__nv_bfloat162*)(Alo + off) = lv;
            }
        }
        cpasync_wait0();
        __syncthreads();

        #pragma unroll
        for (int ks = 0; ks < 4; ks++) {
            uint32_t ah[2][4], al[2][4];
            #pragma unroll
            for (int mt = 0; mt < 2; mt++) {
                int row = warp_m * 32 + mt * 16 + lr + ((g & 1) << 3);
                uint32_t off = sw128((uint32_t)(row * 128 + ((g >> 1) << 4) + ks * 32));
                ldmx4(ah[mt], uAhi + off);
                ldmx4(al[mt], uAlo + off);
            }
            #pragma unroll
            for (int np = 0; np < 6; np++) {
                const int nglob = warp_n * 96 + np * 16;
                const int w     = nglob >> 6;
                const int ncol  = nglob & 63;
                int krow = ks * 16 + ((g & 1) << 3) + lr;
                uint32_t off = sw128((uint32_t)(krow * 128 + (ncol + ((g >> 1) << 3)) * 2));
                uint32_t bh[4], bl[4];
                ldmx4t(bh, uBhi + w * 8192 + off);
                ldmx4t(bl, uBlo + w * 8192 + off);
                #pragma unroll
                for (int mt = 0; mt < 2; mt++) {
                    mma_bf16(c[mt][np * 2],     ah[mt], bh[0], bh[1]);
                    mma_bf16(c[mt][np * 2],     al[mt], bh[0], bh[1]);
                    mma_bf16(c[mt][np * 2],     ah[mt], bl[0], bl[1]);
                    mma_bf16(c[mt][np * 2 + 1], ah[mt], bh[2], bh[3]);
                    mma_bf16(c[mt][np * 2 + 1], al[mt], bh[2], bh[3]);
                    mma_bf16(c[mt][np * 2 + 1], ah[mt], bl[2], bl[3]);
                }
            }
        }
        __syncthreads();
    }

    // ---- epilogue: C frags -> bf16 hi/lo global Q/K/V ----
    {
        __nv_bfloat16* outsH[3] = { g_Qh, g_Kh, g_Vh };
        __nv_bfloat16* outsL[3] = { g_Ql, g_Kl, g_Vl };
        const int crow = lane >> 2;
        const int ccol = (lane & 3) * 2;
        #pragma unroll
        for (int nt = 0; nt < 12; nt++) {
            const int nglob = warp_n * 96 + nt * 8 + ccol;
            __nv_bfloat16* dh = outsH[nglob >> 6];
            __nv_bfloat16* dl = outsL[nglob >> 6];
            const int h = nglob & 63;
            #pragma unroll
            for (int mt = 0; mt < 2; mt++) {
                const int mrow = m0 + warp_m * 32 + mt * 16 + crow;
                #pragma unroll
                for (int rr = 0; rr < 2; rr++) {
                    float v0 = c[mt][nt][rr * 2 + 0];
                    float v1 = c[mt][nt][rr * 2 + 1];
                    __nv_bfloat16 h0 = __float2bfloat16(v0);
                    __nv_bfloat16 h1 = __float2bfloat16(v1);
                    __nv_bfloat16 l0 = __float2bfloat16(v0 - __bfloat162float(h0));
                    __nv_bfloat16 l1 = __float2bfloat16(v1 - __bfloat162float(h1));
                    size_t o = (size_t)(mrow + rr * 8) * Hq + h;
                    __nv_bfloat162 hv; hv.x = h0; hv.y = h1;
                    __nv_bfloat162 lv; lv.x = l0; lv.y = l1;
                    *(__nv_bfloat162*)&dh[o] = hv;
                    *(__nv_bfloat162*)&dl[o] = lv;
                }
            }
        }
    }
}

// ============================================================================
// Kernel 2: causal flash attention via HMMA bf16 3-term split.
// R9: Bc=128 kv chunks (half the iterations/syncs), m/l stats in registers
// (per-warp, wn-duplicated; per-half l partials combined in epilogue).
// 256 threads, 8 warps = 4(M16) x 2(N64 for S / N32 for O).
// Block handles q-tiles qt and 63-qt (33 chunk-iterations total).
// ============================================================================
// smem (bytes): QH 0 (8K), QL 8K, KH 16K (2x16K), KL 48K+..., see offsets.
#define ATTN_SMEM 181248

__global__ __launch_bounds__(256, 1) void attn_kernel(float* __restrict__ out)
{
    extern __shared__ char smb[];
    const uint32_t base = (uint32_t)__cvta_generic_to_shared(smb);
    const uint32_t uQH = base,            uQL = base + 8192;
    const uint32_t uKH = base + 16384,    uKL = base + 49152;   // 2 stages x 16KB
    const uint32_t uVH = base + 81920,    uVL = base + 114688;  // 2 stages x 16KB
    const uint32_t uPH = base + 147456,   uPL = base + 163840;  // 64r x 256B
    float* pm = (float*)(smb + 180224);   // [2][64]
    float* ps = (float*)(smb + 180736);   // [2][64] (epilogue l combine)

    const int tid  = threadIdx.x;
    const int lane = tid & 31;
    const int wid  = tid >> 5;
    const int wm   = wid & 3;           // rows wm*16..+15
    const int wn   = wid >> 2;          // S cols wn*64..+63; O cols wn*32..+31
    const int g    = lane >> 3;
    const int lr   = lane & 7;
    const int r0   = lane >> 2;
    const int cc   = (lane & 3) * 2;
    const int b    = blockIdx.y;

    const int rowA = wm * 16 + r0;
    const int rowB = rowA + 8;

    #pragma unroll 1
    for (int half = 0; half < 2; half++) {
        const int qt = (half == 0) ? (int)blockIdx.x : 63 - (int)blockIdx.x;
        const int nck = (qt >> 1) + 1;      // 128-wide kv chunks
        __syncthreads();   // previous half fully done with smem

        const size_t qoff   = ((size_t)b * Sq + (size_t)qt * 64) * Hq;
        const size_t kvbase = (size_t)b * Sq * Hq;

        // prologue: Q hi/lo + kv-chunk 0 (stage 0)
        #pragma unroll
        for (int it = 0; it < 2; it++) {
            int chunk = tid + it * 256;         // 0..511
            int r = chunk >> 3, c16 = chunk & 7;
            uint32_t off = sw128((uint32_t)(r * 128 + c16 * 16));
            size_t gsrc = (size_t)r * 64 + c16 * 8;
            cpasync16(uQH + off, g_Qh + qoff + gsrc);
            cpasync16(uQL + off, g_Ql + qoff + gsrc);
        }
        #pragma unroll
        for (int it = 0; it < 4; it++) {
            int chunk = tid + it * 256;         // 0..1023
            int r = chunk >> 3, c16 = chunk & 7;
            uint32_t off = sw128((uint32_t)(r * 128 + c16 * 16));
            size_t gsrc = (size_t)r * 64 + c16 * 8;
            cpasync16(uKH + off, g_Kh + kvbase + gsrc);
            cpasync16(uKL + off, g_Kl + kvbase + gsrc);
            cpasync16(uVH + off, g_Vh + kvbase + gsrc);
            cpasync16(uVL + off, g_Vl + kvbase + gsrc);
        }
        cpasync_commit();

        float mA = -1e30f, mB = -1e30f, lA = 0.0f, lB = 0.0f;
        float c[4][4];
        #pragma unroll
        for (int np = 0; np < 4; np++)
            #pragma unroll
            for (int e = 0; e < 4; e++) c[np][e] = 0.0f;

        cpasync_wait0();
        __syncthreads();

        #pragma unroll 1
        for (int ck = 0; ck < nck; ck++) {
            const int cur = ck & 1;
            const uint32_t kh = uKH + cur * 16384, kl = uKL + cur * 16384;
            const uint32_t vh = uVH + cur * 16384, vl = uVL + cur * 16384;

            if (ck < nck - 1) {   // prefetch next kv chunk into alternate stage
                size_t nsrc = kvbase + (size_t)(ck + 1) * 128 * Hq;
                uint32_t boff = (uint32_t)(1 - cur) * 16384;
                #pragma unroll
                for (int it = 0; it < 4; it++) {
                    int chunk = tid + it * 256;
                    int r = chunk >> 3, c16 = chunk & 7;
                    uint32_t off = sw128((uint32_t)(r * 128 + c16 * 16));
                    size_t gsrc = (size_t)r * 64 + c16 * 8;
                    cpasync16(uKH + boff + off, g_Kh + nsrc + gsrc);
                    cpasync16(uKL + boff + off, g_Kl + nsrc + gsrc);
                    cpasync16(uVH + boff + off, g_Vh + nsrc + gsrc);
                    cpasync16(uVL + boff + off, g_Vl + nsrc + gsrc);
                }
                cpasync_commit();
            }

            // ---- S = Q K^T : warp covers 16 rows x 64 kv cols (wn half) ----
            float s[8][4];
            #pragma unroll
            for (int np = 0; np < 8; np++)
                #pragma unroll
                for (int e = 0; e < 4; e++) s[np][e] = 0.0f;

            #pragma unroll
            for (int ks = 0; ks < 4; ks++) {
                uint32_t ah[4], al[4];
                {
                    uint32_t off = sw128((uint32_t)((wm * 16 + lr + ((g & 1) << 3)) * 128
                                                    + ((g >> 1) << 4) + ks * 32));
                    ldmx4(ah, uQH + off);
                    ldmx4(al, uQL + off);
                }
                #pragma unroll
                for (int ng = 0; ng < 4; ng++) {
                    int nb = wn * 64 + ng * 16;
                    uint32_t off = sw128((uint32_t)((nb + ((g >> 1) << 3) + lr) * 128
                                                    + ((g & 1) << 4) + ks * 32));
                    uint32_t bh[4], bl[4];
                    ldmx4(bh, kh + off);
                    ldmx4(bl, kl + off);
                    mma_bf16(s[ng * 2],     ah, bh[0], bh[1]);
                    mma_bf16(s[ng * 2],     al, bh[0], bh[1]);
                    mma_bf16(s[ng * 2],     ah, bl[0], bl[1]);
                    mma_bf16(s[ng * 2 + 1], ah, bh[2], bh[3]);
                    mma_bf16(s[ng * 2 + 1], al, bh[2], bh[3]);
                    mma_bf16(s[ng * 2 + 1], ah, bl[2], bl[3]);
                }
            }

            // ---- scale + causal mask (only on diagonal chunk) ----
            const float SCL = 0.125f * 1.44269504089f;
            if (ck == (qt >> 1)) {
                const int gi0 = qt * 64 + rowA;
                const int gi1 = gi0 + 8;
                #pragma unroll
                for (int np = 0; np < 8; np++) {
                    int gj = ck * 128 + wn * 64 + np * 8 + cc;
                    s[np][0] = (gj     > gi0) ? -1e30f : s[np][0] * SCL;
                    s[np][1] = (gj + 1 > gi0) ? -1e30f : s[np][1] * SCL;
                    s[np][2] = (gj     > gi1) ? -1e30f : s[np][2] * SCL;
                    s[np][3] = (gj + 1 > gi1) ? -1e30f : s[np][3] * SCL;
                }
            } else {
                #pragma unroll
                for (int np = 0; np < 8; np++)
                    #pragma unroll
                    for (int e = 0; e < 4; e++) s[np][e] *= SCL;
            }

            // ---- partial rowmax (quad shuffle) -> pm ----
            float rm0 = -1e30f, rm1 = -1e30f;
            #pragma unroll
            for (int np = 0; np < 8; np++) {
                rm0 = fmaxf(rm0, fmaxf(s[np][0], s[np][1]));
                rm1 = fmaxf(rm1, fmaxf(s[np][2], s[np][3]));
            }
            rm0 = fmaxf(rm0, __shfl_xor_sync(0xffffffffu, rm0, 1));
            rm0 = fmaxf(rm0, __shfl_xor_sync(0xffffffffu, rm0, 2));
            rm1 = fmaxf(rm1, __shfl_xor_sync(0xffffffffu, rm1, 1));
            rm1 = fmaxf(rm1, __shfl_xor_sync(0xffffffffu, rm1, 2));
            if ((lane & 3) == 0) {
                pm[wn * 64 + rowA] = rm0;
                pm[wn * 64 + rowB] = rm1;
            }
            __syncthreads();   // SYNC0: pm visible (also: prev P reads done)

            // ---- softmax: regs only; P hi/lo -> smem ----
            const float mn0 = fmaxf(mA, fmaxf(pm[rowA], pm[64 + rowA]));
            const float mn1 = fmaxf(mB, fmaxf(pm[rowB], pm[64 + rowB]));
            float rs0 = 0.0f, rs1 = 0.0f;
            #pragma unroll
            for (int np = 0; np < 8; np++) {
                s[np][0] = exp2f(s[np][0] - mn0);
                s[np][1] = exp2f(s[np][1] - mn0);
                s[np][2] = exp2f(s[np][2] - mn1);
                s[np][3] = exp2f(s[np][3] - mn1);
                rs0 += s[np][0] + s[np][1];
                rs1 += s[np][2] + s[np][3];
                int col = wn * 64 + np * 8 + cc;     // kv col in 0..127
                int chk = col >> 3;
                int cb  = (col & 7) * 2;
                float h0f = __bfloat162float(__float2bfloat16(s[np][0]));
                float h1f = __bfloat162float(__float2bfloat16(s[np][1]));
                float h2f = __bfloat162float(__float2bfloat16(s[np][2]));
                float h3f = __bfloat162float(__float2bfloat16(s[np][3]));
                uint32_t offA = swP(rowA, chk) + cb;
                uint32_t offB = swP(rowB, chk) + cb;
                sts32(uPH + offA, bfpack(h0f, h1f));
                sts32(uPH + offB, bfpack(h2f, h3f));
                sts32(uPL + offA, bfpack(s[np][0] - h0f, s[np][1] - h1f));
                sts32(uPL + offB, bfpack(s[np][2] - h2f, s[np][3] - h3f));
            }
            rs0 += __shfl_xor_sync(0xffffffffu, rs0, 1);
            rs0 += __shfl_xor_sync(0xffffffffu, rs0, 2);
            rs1 += __shfl_xor_sync(0xffffffffu, rs1, 1);
            rs1 += __shfl_xor_sync(0xffffffffu, rs1, 2);

            // ---- stats + O rescale (all in registers) ----
            {
                const float f0 = exp2f(mA - mn0);
                const float f1 = exp2f(mB - mn1);
                lA = lA * f0 + rs0;  mA = mn0;
                lB = lB * f1 + rs1;  mB = mn1;
                #pragma unroll
                for (int np = 0; np < 4; np++) {
                    c[np][0] *= f0; c[np][1] *= f0;
                    c[np][2] *= f1; c[np][3] *= f1;
                }
            }
            __syncthreads();   // SYNC1: P visible

            // ---- O += P V : warp computes O[16 x 32 head cols (wn half)] ----
            #pragma unroll
            for (int ks = 0; ks < 8; ks++) {
                uint32_t pah[4], pal[4];
                {
                    int prow = wm * 16 + lr + ((g & 1) << 3);
                    int pchk = ks * 2 + (g >> 1);
                    uint32_t off = swP(prow, pchk);
                    ldmx4(pah, uPH + off);
                    ldmx4(pal, uPL + off);
                }
                #pragma unroll
                for (int ng = 0; ng < 2; ng++) {
                    int nb = wn * 32 + ng * 16;
                    int krow = ks * 16 + ((g & 1) << 3) + lr;
                    uint32_t off = sw128((uint32_t)(krow * 128
                                                    + (nb + ((g >> 1) << 3)) * 2));
                    uint32_t bh[4], bl[4];
                    ldmx4t(bh, vh + off);
                    ldmx4t(bl, vl + off);
                    mma_bf16(c[ng * 2],     pah, bh[0], bh[1]);
                    mma_bf16(c[ng * 2],     pal, bh[0], bh[1]);
                    mma_bf16(c[ng * 2],     pah, bl[0], bl[1]);
                    mma_bf16(c[ng * 2 + 1], pah, bh[2], bh[3]);
                    mma_bf16(c[ng * 2 + 1], pal, bh[2], bh[3]);
                    mma_bf16(c[ng * 2 + 1], pah, bl[2], bl[3]);
                }
            }

            if (ck < nck - 1) cpasync_wait0();
            __syncthreads();   // SYNC2: stages safe for next iteration
        }

        // ---- epilogue: combine l halves, O /= l, write out ----
        if ((lane & 3) == 0) {
            ps[wn * 64 + rowA] = lA;
            ps[wn * 64 + rowB] = lB;
        }
        __syncthreads();
        {
            const float inv0 = 1.0f / (ps[rowA] + ps[64 + rowA]);
            const float inv1 = 1.0f / (ps[rowB] + ps[64 + rowB]);
            #pragma unroll
            for (int np = 0; np < 4; np++) {
                int hcol = wn * 32 + np * 8 + cc;
                float2 v0 = { c[np][0] * inv0, c[np][1] * inv0 };
                float2 v1 = { c[np][2] * inv1, c[np][3] * inv1 };
                *(float2*)&out[((size_t)b * Sq + (size_t)qt * 64 + rowA) * Hq + hcol] = v0;
                *(float2*)&out[((size_t)b * Sq + (size_t)qt * 64 + rowB) * Hq + hcol] = v1;
            }
        }
    }
}

// ============================================================================
extern "C" void kernel_launch(void* const* d_in, const int* in_sizes, int n_in,
                              void* d_out, int out_size)
{
    const float* x  = (const float*)d_in[0];
    const float* Wq = (const float*)d_in[1];
    const float* Wk = (const float*)d_in[2];
    const float* Wv = (const float*)d_in[3];
    float* out = (float*)d_out;

    cudaFuncSetAttribute(qkv_kernel, cudaFuncAttributeMaxDynamicSharedMemorySize,
                         QKV_SMEM);
    cudaFuncSetAttribute(attn_kernel, cudaFuncAttributeMaxDynamicSharedMemorySize,
                         ATTN_SMEM);

    wprep_kernel<<<148, 256>>>(Wq, Wk, Wv);
    qkv_kernel<<<128, 256, QKV_SMEM>>>(x);
    attn_kernel<<<dim3(32, 4), 256, ATTN_SMEM>>>(out);
}